// round 13
// baseline (speedup 1.0000x reference)
#include <cuda_runtime.h>
#include <cuda_fp16.h>
#include <cstdint>

#define DD    64
#define HID   128
#define NCLS  5
#define MAXU  100000
#define MAXM  50000

// Scratch (allocation-free per harness rules). U/I stored as fp16.
__device__ unsigned short g_Uh[(size_t)MAXU * HID];   // 25.6 MB
__device__ unsigned short g_Ih[(size_t)MAXM * HID];   // 12.8 MB

// ---- packed f32x2 helpers (sm_100) ----
__device__ __forceinline__ unsigned long long ffma2(unsigned long long a,
                                                    unsigned long long b,
                                                    unsigned long long c) {
    unsigned long long d;
    asm("fma.rn.f32x2 %0, %1, %2, %3;" : "=l"(d) : "l"(a), "l"(b), "l"(c));
    return d;
}
__device__ __forceinline__ float2 u2f(unsigned long long v) {
    float2 r;
    asm("mov.b64 {%0, %1}, %2;" : "=f"(r.x), "=f"(r.y) : "l"(v));
    return r;
}

// Wt 16B-chunk XOR swizzle keyed on (k>>2) (R12-proven): fill stores have
// k = 4f+q so the key carries full lane entropy -> conflict-free transpose
// stores; compute reads are a per-k bijection of 16B chunks.
#define SWF(k, fi) ((((((fi) >> 2) ^ (((k) >> 2) & 7))) << 2) | ((fi) & 3))

// Fsd (duplicated F) swizzle: row r lives as an 8B dup pair; chunk = r>>1,
// XOR'd with (k>>2)&7. Fill: the 2 lanes sharing a bank-quad (r even/odd)
// use disjoint banks within it -> conflict-free STS.64. Compute: address
// depends only on tr -> 2-address multicast LDS.128.
#define DSWF(k, r) (((((r) >> 1) ^ (((k) >> 2) & 7)) << 2) | (((r) & 1) << 1))

// ---------------------------------------------------------------------------
// Pre v6: register-tiled GEMM; F stored DUPLICATED in smem so the inner loop
// has zero packing MOVs (W pairs come naturally adjacent from Wt).
// Block = 256 threads (16tr x 16tc), thread tile 8 rows x 8 cols, k=64 in
// 2 halves of 32. Per k: 4 LDS.128 (F dup pairs) + 2 LDS.128 (W col pairs)
// + 32 FFMA2. Scalar accumulation chains identical to pre2/pre5 ->
// bit-identical U/I.
//   Fsd[32][256]  32KB  [k][dup'd row]
//   Wt [32][128]  16KB  [k][col]        (total 48KB exactly)
// ---------------------------------------------------------------------------
__global__ void __launch_bounds__(256, 2)
pre6_kernel(const float* __restrict__ ufeat, const float* __restrict__ ifeat,
            const float* __restrict__ W1, const float* __restrict__ b1,
            int nu, int nm, int blocksU) {
    __shared__ __align__(16) float Fsd[32 * 256];  // 32KB
    __shared__ __align__(16) float Wt[32 * 128];   // 16KB

    bool isU = (int)blockIdx.x < blocksU;
    int rowbase = (isU ? blockIdx.x : blockIdx.x - blocksU) * 128;
    int nrows = isU ? nu : nm;
    const float4* F4 = (const float4*)(isU ? ufeat : ifeat);   // row = 16 float4
    const float4* W14 = (const float4*)W1;                     // row = 32 float4
    int woff = isU ? 0 : 16;
    unsigned short* outb = isU ? g_Uh : g_Ih;

    int tid = threadIdx.x;
    int tr = tid >> 4, tc = tid & 15;
    int r0 = tr * 8, c0 = tc * 8;

    unsigned long long acc[8][4];   // acc[row][colpair]
#pragma unroll
    for (int a = 0; a < 8; a++)
#pragma unroll
        for (int j = 0; j < 4; j++) acc[a][j] = 0ULL;

#pragma unroll
    for (int h = 0; h < 2; h++) {
        if (h) __syncthreads();
#pragma unroll
        for (int it = 0; it < 4; it++) {
            int idx = it * 256 + tid;        // 0..1023
            int r = idx >> 3;                // 0..127 (row or col)
            int f = idx & 7;                 // float4 within k-half
            int kq = f * 4;
            int rr = rowbase + r;
            if (rr >= nrows) rr = nrows - 1;
            float4 v = F4[(size_t)rr * 16 + h * 8 + f];
            *(float2*)&Fsd[(kq + 0) * 256 + DSWF(kq + 0, r)] = make_float2(v.x, v.x);
            *(float2*)&Fsd[(kq + 1) * 256 + DSWF(kq + 1, r)] = make_float2(v.y, v.y);
            *(float2*)&Fsd[(kq + 2) * 256 + DSWF(kq + 2, r)] = make_float2(v.z, v.z);
            *(float2*)&Fsd[(kq + 3) * 256 + DSWF(kq + 3, r)] = make_float2(v.w, v.w);
            float4 u = W14[(size_t)r * 32 + woff + h * 8 + f];
            Wt[(kq + 0) * 128 + SWF(kq + 0, r)] = u.x;
            Wt[(kq + 1) * 128 + SWF(kq + 1, r)] = u.y;
            Wt[(kq + 2) * 128 + SWF(kq + 2, r)] = u.z;
            Wt[(kq + 3) * 128 + SWF(kq + 3, r)] = u.w;
        }
        __syncthreads();

#pragma unroll 4
        for (int k = 0; k < 32; k++) {
            // 8 dup'd rows: 4 LDS.128, chunk (4tr+i)^key holds rows 2i, 2i+1
            unsigned long long fd[8];
#pragma unroll
            for (int i = 0; i < 4; i++) {
                ulonglong2 t = *(const ulonglong2*)
                    &Fsd[k * 256 + ((((4 * tr + i) ^ ((k >> 2) & 7)) << 2))];
                fd[2 * i] = t.x;
                fd[2 * i + 1] = t.y;
            }
            // 4 natural col pairs: 2 LDS.128
            ulonglong2 wp0 = *(const ulonglong2*)&Wt[k * 128 + SWF(k, c0)];
            ulonglong2 wp1 = *(const ulonglong2*)&Wt[k * 128 + SWF(k, c0 + 4)];
            unsigned long long wd[4];
            wd[0] = wp0.x; wd[1] = wp0.y; wd[2] = wp1.x; wd[3] = wp1.y;
#pragma unroll
            for (int r = 0; r < 8; r++)
#pragma unroll
                for (int cp = 0; cp < 4; cp++)
                    acc[r][cp] = ffma2(fd[r], wd[cp], acc[r][cp]);
        }
    }

    float bv[8];
#pragma unroll
    for (int j = 0; j < 8; j++) bv[j] = 0.f;
    if (!isU) {
#pragma unroll
        for (int j = 0; j < 8; j++) bv[j] = b1[c0 + j];
    }

    // acc[r][cp] = (out[r][c0+2cp], out[r][c0+2cp+1]) -> one 16B store per row
#pragma unroll
    for (int r = 0; r < 8; r++) {
        int row = rowbase + r0 + r;
        if (row < nrows) {
            unsigned res[4];
#pragma unroll
            for (int cp = 0; cp < 4; cp++) {
                float2 t = u2f(acc[r][cp]);
                __half2 hh = __floats2half2_rn(t.x + bv[2 * cp],
                                               t.y + bv[2 * cp + 1]);
                res[cp] = *(unsigned*)&hh;
            }
            *(uint4*)(outb + (size_t)row * HID + c0) =
                make_uint4(res[0], res[1], res[2], res[3]);
        }
    }
}

// ---------------------------------------------------------------------------
// Edge MMA kernel (R9/R12-proven, 52.8us — unchanged). 16-edge chunks per
// warp, coalesced line-granular gather, fp16 relu-add, ldmatrix +
// mma.m16n8k16 vs register-resident W2 fragments, fp32 accumulate.
// ---------------------------------------------------------------------------
__device__ __forceinline__ unsigned su32(const void* p) {
    return (unsigned)__cvta_generic_to_shared(p);
}

__global__ void __launch_bounds__(256, 3)
edge_mma_kernel(const float* __restrict__ W2, const float* __restrict__ b2,
                const void* __restrict__ srcraw, const void* __restrict__ dstraw,
                float* __restrict__ out, long E) {
    __shared__ __align__(128) unsigned char hs[8 * 16 * 256];  // 32KB, 4KB/warp

    int tid = threadIdx.x;
    int w = tid >> 5, lane = tid & 31;
    unsigned char* hp = hs + w * 4096;

    // ---- inline is64 probe (identical result in every warp) ----
    long n64avail = E / 2;
    int pid = (lane < n64avail) ? lane : 0;
    unsigned long long pv = ((const unsigned long long*)srcraw)[pid];
    unsigned bigmask = __ballot_sync(0xffffffffu, pv >= 200000ULL);
    int is64 = (bigmask == 0u);

    // ---- B fragments: W2 as fp16 in mma.m16n8k16 col layout, built once ----
    int nB = lane >> 2;
    int kb = (lane & 3) * 2;
    unsigned bfrag[8][2];
#pragma unroll
    for (int kt = 0; kt < 8; kt++) {
#pragma unroll
        for (int j = 0; j < 2; j++) {
            int k0 = kt * 16 + kb + j * 8;
            float f0 = (nB < NCLS) ? __ldg(W2 + nB * HID + k0) : 0.f;
            float f1 = (nB < NCLS) ? __ldg(W2 + nB * HID + k0 + 1) : 0.f;
            __half2 hh = __floats2half2_rn(f0, f1);
            bfrag[kt][j] = *(unsigned*)&hh;
        }
    }
    int cA = (lane & 3) * 2, cB = cA + 1;
    float bA = (cA < NCLS) ? __ldg(b2 + cA) : 0.f;
    float bB = (cB < NCLS) ? __ldg(b2 + cB) : 0.f;

    int g = lane >> 3, hl = lane & 7;
    __half2 z2 = __float2half2_rn(0.f);

    long chunk0 = ((long)blockIdx.x * 8 + w) * 16;
    long stride = (long)gridDim.x * 8 * 16;

    for (long e0 = chunk0; e0 < E; e0 += stride) {
        // ---- gather 16 edges into the warp's smem tile (coalesced) ----
#pragma unroll
        for (int p = 0; p < 4; p++) {
            long e = e0 + p * 4 + g;
            long ec = (e < E) ? e : E - 1;
            int s = is64 ? (int)__ldg((const long long*)srcraw + ec)
                         : __ldg((const int*)srcraw + ec);
            int d = is64 ? (int)__ldg((const long long*)dstraw + ec)
                         : __ldg((const int*)dstraw + ec);
            const uint4* Up = (const uint4*)g_Uh + (size_t)s * 16;
            const uint4* Ip = (const uint4*)g_Ih + (size_t)d * 16;
            uint4 u0 = Up[hl], u1 = Up[hl + 8];     // line 0 / line 1
            uint4 v0 = Ip[hl], v1 = Ip[hl + 8];

            uint4 ra, rb;
            {
                const __half2* ua = (const __half2*)&u0;
                const __half2* va = (const __half2*)&v0;
                __half2 h0 = __hmax2(__hadd2(ua[0], va[0]), z2);
                __half2 h1 = __hmax2(__hadd2(ua[1], va[1]), z2);
                __half2 h2 = __hmax2(__hadd2(ua[2], va[2]), z2);
                __half2 h3 = __hmax2(__hadd2(ua[3], va[3]), z2);
                ra = make_uint4(*(unsigned*)&h0, *(unsigned*)&h1,
                                *(unsigned*)&h2, *(unsigned*)&h3);
                const __half2* ub = (const __half2*)&u1;
                const __half2* vb = (const __half2*)&v1;
                __half2 h4 = __hmax2(__hadd2(ub[0], vb[0]), z2);
                __half2 h5 = __hmax2(__hadd2(ub[1], vb[1]), z2);
                __half2 h6 = __hmax2(__hadd2(ub[2], vb[2]), z2);
                __half2 h7 = __hmax2(__hadd2(ub[3], vb[3]), z2);
                rb = make_uint4(*(unsigned*)&h4, *(unsigned*)&h5,
                                *(unsigned*)&h6, *(unsigned*)&h7);
            }
            int r = p * 4 + g;                 // row in tile 0..15
            unsigned sw = (unsigned)((r & 7) << 4);
            unsigned off0 = r * 256 + ((hl * 16) ^ sw);          // k 0..63
            unsigned off1 = r * 256 + ((128 + hl * 16) ^ sw);    // k 64..127
            *(uint4*)(hp + off0) = ra;
            *(uint4*)(hp + off1) = rb;
        }
        __syncwarp();

        // ---- mma over k=128 ----
        float acc0 = 0.f, acc1 = 0.f, acc2 = 0.f, acc3 = 0.f;
        int rr = (lane & 7) + ((lane >> 3) & 1) * 8;   // ldmatrix row
        int khalf = (lane >> 4) * 16;                  // 0 or 16 bytes
        unsigned rowsw = (unsigned)((rr & 7) << 4);
        unsigned abase = su32(hp) + rr * 256;
#pragma unroll
        for (int kt = 0; kt < 8; kt++) {
            unsigned addr = abase + (((unsigned)(kt * 32 + khalf)) ^ rowsw);
            unsigned a0, a1, a2, a3;
            asm volatile("ldmatrix.sync.aligned.m8n8.x4.shared.b16 "
                         "{%0,%1,%2,%3}, [%4];"
                         : "=r"(a0), "=r"(a1), "=r"(a2), "=r"(a3)
                         : "r"(addr));
            asm volatile("mma.sync.aligned.m16n8k16.row.col.f32.f16.f16.f32 "
                         "{%0,%1,%2,%3}, {%4,%5,%6,%7}, {%8,%9}, {%0,%1,%2,%3};"
                         : "+f"(acc0), "+f"(acc1), "+f"(acc2), "+f"(acc3)
                         : "r"(a0), "r"(a1), "r"(a2), "r"(a3),
                           "r"(bfrag[kt][0]), "r"(bfrag[kt][1]));
        }
        __syncwarp();   // protect smem WAR vs next chunk's gather

        // ---- store: c0/c1 -> row lane>>2, cols cA/cB; c2/c3 -> row+8 ----
        long eA = e0 + (lane >> 2);
        long eBr = eA + 8;
        if (cA < NCLS) {
            if (eA < E)  out[eA * NCLS + cA] = acc0 + bA;
            if (eBr < E) out[eBr * NCLS + cA] = acc2 + bA;
        }
        if (cB < NCLS) {
            if (eA < E)  out[eA * NCLS + cB] = acc1 + bB;
            if (eBr < E) out[eBr * NCLS + cB] = acc3 + bB;
        }
    }
}

// ---------------------------------------------------------------------------
// Inputs (metadata order): ufeat, ifeat, W1, b1, W2, b2, src_idx, dst_idx
// ---------------------------------------------------------------------------
extern "C" void kernel_launch(void* const* d_in, const int* in_sizes, int n_in,
                              void* d_out, int out_size) {
    const float* ufeat = (const float*)d_in[0];
    const float* ifeat = (const float*)d_in[1];
    const float* W1    = (const float*)d_in[2];
    const float* b1    = (const float*)d_in[3];
    const float* W2    = (const float*)d_in[4];
    const float* b2    = (const float*)d_in[5];
    const void*  src   = d_in[6];
    const void*  dst   = d_in[7];

    int nu = in_sizes[0] / DD;
    int nm = in_sizes[1] / DD;
    int E  = in_sizes[6];

    int blocksU = (nu + 127) / 128;
    int blocksI = (nm + 127) / 128;
    pre6_kernel<<<blocksU + blocksI, 256>>>(ufeat, ifeat, W1, b1, nu, nm, blocksU);

    edge_mma_kernel<<<444, 256>>>(W2, b2, src, dst, (float*)d_out, (long)E);
}

// round 14
// speedup vs baseline: 1.6778x; 1.6778x over previous
#include <cuda_runtime.h>
#include <cuda_fp16.h>
#include <cstdint>

#define DD    64
#define HID   128
#define NCLS  5
#define MAXU  100000
#define MAXM  50000

// Scratch (allocation-free per harness rules). U/I stored as fp16.
__device__ unsigned short g_Uh[(size_t)MAXU * HID];   // 25.6 MB
__device__ unsigned short g_Ih[(size_t)MAXM * HID];   // 12.8 MB

__device__ __forceinline__ unsigned su32(const void* p) {
    return (unsigned)__cvta_generic_to_shared(p);
}

// ---------------------------------------------------------------------------
// Pre MMA kernel: U/I = feat @ W1halfT (+b1) on tensor cores.
// Block = 256 thr = 8 warps, tile M=128 rows x N=128 cols, K=64.
// Warp grid 4(m) x 2(n): warp tile 32 rows x 64 cols.
// A (feat) and B (W1 half) converted to fp16 in smem, 128B rows,
// XOR-16B swizzle keyed on (row&7) — the exact layout the edge kernel's
// ldmatrix path already validates. B-fragments built by scalar LDS.32
// (conflict-free: 8 chunks x 4 words = 32 banks). fp32 accumulate.
// ---------------------------------------------------------------------------
__global__ void __launch_bounds__(256, 2)
pre_mma_kernel(const float* __restrict__ ufeat, const float* __restrict__ ifeat,
               const float* __restrict__ W1, const float* __restrict__ b1,
               int nu, int nm, int blocksU) {
    __shared__ __align__(128) unsigned char As[128 * 128];  // 16KB fp16 feat tile
    __shared__ __align__(128) unsigned char Bs[128 * 128];  // 16KB fp16 W1 tile

    bool isU = (int)blockIdx.x < blocksU;
    int rowbase = (isU ? blockIdx.x : blockIdx.x - blocksU) * 128;
    int nrows = isU ? nu : nm;
    const float4* F4 = (const float4*)(isU ? ufeat : ifeat);   // row = 16 float4
    const float4* W14 = (const float4*)W1;                     // row = 32 float4
    int woff = isU ? 0 : 16;
    unsigned short* outb = isU ? g_Uh : g_Ih;

    int tid = threadIdx.x;
    int w = tid >> 5, lane = tid & 31;

    // ---- fill: fp32 -> fp16, swizzled 128B rows ----
#pragma unroll
    for (int it = 0; it < 8; it++) {
        int idx = it * 256 + tid;          // 0..2047
        int r = idx >> 4;                  // 0..127
        int f = idx & 15;                  // float4 within row
        int rr = rowbase + r;
        if (rr >= nrows) rr = nrows - 1;
        unsigned swo = (unsigned)((f * 8) ^ ((r & 7) << 4));
        float4 v = F4[(size_t)rr * 16 + f];
        __half2 a01 = __floats2half2_rn(v.x, v.y);
        __half2 a23 = __floats2half2_rn(v.z, v.w);
        *(uint2*)(As + r * 128 + swo) =
            make_uint2(*(unsigned*)&a01, *(unsigned*)&a23);
        float4 u = W14[(size_t)r * 32 + woff + f];
        __half2 b01 = __floats2half2_rn(u.x, u.y);
        __half2 b23 = __floats2half2_rn(u.z, u.w);
        *(uint2*)(Bs + r * 128 + swo) =
            make_uint2(*(unsigned*)&b01, *(unsigned*)&b23);
    }
    __syncthreads();

    int warp_m = w & 3;    // 0..3 -> rows warp_m*32
    int warp_n = w >> 2;   // 0..1 -> cols warp_n*64

    float acc[2][8][4];
#pragma unroll
    for (int m = 0; m < 2; m++)
#pragma unroll
        for (int nt = 0; nt < 8; nt++)
#pragma unroll
            for (int j = 0; j < 4; j++) acc[m][nt][j] = 0.f;

    // ldmatrix lane addressing (identical pattern to edge kernel)
    int rr_ld = (lane & 7) + ((lane >> 3) & 1) * 8;
    int khalf = (lane >> 4) * 16;
    unsigned rowsw = (unsigned)((rr_ld & 7) << 4);
    unsigned abase0 = su32(As) + (warp_m * 32 + rr_ld) * 128;
    unsigned abase1 = abase0 + 16 * 128;

#pragma unroll
    for (int kt = 0; kt < 4; kt++) {
        unsigned a0[4], a1[4];
        unsigned kk = (unsigned)(kt * 32 + khalf) ^ rowsw;
        asm volatile("ldmatrix.sync.aligned.m8n8.x4.shared.b16 "
                     "{%0,%1,%2,%3}, [%4];"
                     : "=r"(a0[0]), "=r"(a0[1]), "=r"(a0[2]), "=r"(a0[3])
                     : "r"(abase0 + kk));
        asm volatile("ldmatrix.sync.aligned.m8n8.x4.shared.b16 "
                     "{%0,%1,%2,%3}, [%4];"
                     : "=r"(a1[0]), "=r"(a1[1]), "=r"(a1[2]), "=r"(a1[3])
                     : "r"(abase1 + kk));
#pragma unroll
        for (int nt = 0; nt < 8; nt++) {
            int brow = warp_n * 64 + nt * 8 + (lane >> 2);
            unsigned bswz = (unsigned)((brow & 7) << 4);
            unsigned obase = (unsigned)(brow * 128);
            unsigned b0 = *(const unsigned*)
                (Bs + obase + (((unsigned)(kt * 32 + (lane & 3) * 4)) ^ bswz));
            unsigned b1r = *(const unsigned*)
                (Bs + obase + (((unsigned)(kt * 32 + 16 + (lane & 3) * 4)) ^ bswz));
            asm volatile("mma.sync.aligned.m16n8k16.row.col.f32.f16.f16.f32 "
                         "{%0,%1,%2,%3}, {%4,%5,%6,%7}, {%8,%9}, {%0,%1,%2,%3};"
                         : "+f"(acc[0][nt][0]), "+f"(acc[0][nt][1]),
                           "+f"(acc[0][nt][2]), "+f"(acc[0][nt][3])
                         : "r"(a0[0]), "r"(a0[1]), "r"(a0[2]), "r"(a0[3]),
                           "r"(b0), "r"(b1r));
            asm volatile("mma.sync.aligned.m16n8k16.row.col.f32.f16.f16.f32 "
                         "{%0,%1,%2,%3}, {%4,%5,%6,%7}, {%8,%9}, {%0,%1,%2,%3};"
                         : "+f"(acc[1][nt][0]), "+f"(acc[1][nt][1]),
                           "+f"(acc[1][nt][2]), "+f"(acc[1][nt][3])
                         : "r"(a1[0]), "r"(a1[1]), "r"(a1[2]), "r"(a1[3]),
                           "r"(b0), "r"(b1r));
        }
    }

    // ---- epilogue: +bias (I side), fp16, store ----
#pragma unroll
    for (int nt = 0; nt < 8; nt++) {
        int col = warp_n * 64 + nt * 8 + 2 * (lane & 3);
        float biasA = 0.f, biasB = 0.f;
        if (!isU) { biasA = __ldg(b1 + col); biasB = __ldg(b1 + col + 1); }
#pragma unroll
        for (int m = 0; m < 2; m++) {
            int rA = rowbase + warp_m * 32 + m * 16 + (lane >> 2);
            int rB = rA + 8;
            if (rA < nrows) {
                __half2 hh = __floats2half2_rn(acc[m][nt][0] + biasA,
                                               acc[m][nt][1] + biasB);
                *(unsigned*)(outb + (size_t)rA * HID + col) = *(unsigned*)&hh;
            }
            if (rB < nrows) {
                __half2 hh = __floats2half2_rn(acc[m][nt][2] + biasA,
                                               acc[m][nt][3] + biasB);
                *(unsigned*)(outb + (size_t)rB * HID + col) = *(unsigned*)&hh;
            }
        }
    }
}

// ---------------------------------------------------------------------------
// Edge MMA kernel (R9/R12-proven, 52.8us — unchanged). 16-edge chunks per
// warp, coalesced line-granular gather, fp16 relu-add, ldmatrix +
// mma.m16n8k16 vs register-resident W2 fragments, fp32 accumulate.
// ---------------------------------------------------------------------------
__global__ void __launch_bounds__(256, 3)
edge_mma_kernel(const float* __restrict__ W2, const float* __restrict__ b2,
                const void* __restrict__ srcraw, const void* __restrict__ dstraw,
                float* __restrict__ out, long E) {
    __shared__ __align__(128) unsigned char hs[8 * 16 * 256];  // 32KB, 4KB/warp

    int tid = threadIdx.x;
    int w = tid >> 5, lane = tid & 31;
    unsigned char* hp = hs + w * 4096;

    // ---- inline is64 probe (identical result in every warp) ----
    long n64avail = E / 2;
    int pid = (lane < n64avail) ? lane : 0;
    unsigned long long pv = ((const unsigned long long*)srcraw)[pid];
    unsigned bigmask = __ballot_sync(0xffffffffu, pv >= 200000ULL);
    int is64 = (bigmask == 0u);

    // ---- B fragments: W2 as fp16 in mma.m16n8k16 col layout, built once ----
    int nB = lane >> 2;
    int kb = (lane & 3) * 2;
    unsigned bfrag[8][2];
#pragma unroll
    for (int kt = 0; kt < 8; kt++) {
#pragma unroll
        for (int j = 0; j < 2; j++) {
            int k0 = kt * 16 + kb + j * 8;
            float f0 = (nB < NCLS) ? __ldg(W2 + nB * HID + k0) : 0.f;
            float f1 = (nB < NCLS) ? __ldg(W2 + nB * HID + k0 + 1) : 0.f;
            __half2 hh = __floats2half2_rn(f0, f1);
            bfrag[kt][j] = *(unsigned*)&hh;
        }
    }
    int cA = (lane & 3) * 2, cB = cA + 1;
    float bA = (cA < NCLS) ? __ldg(b2 + cA) : 0.f;
    float bB = (cB < NCLS) ? __ldg(b2 + cB) : 0.f;

    int g = lane >> 3, hl = lane & 7;
    __half2 z2 = __float2half2_rn(0.f);

    long chunk0 = ((long)blockIdx.x * 8 + w) * 16;
    long stride = (long)gridDim.x * 8 * 16;

    for (long e0 = chunk0; e0 < E; e0 += stride) {
        // ---- gather 16 edges into the warp's smem tile (coalesced) ----
#pragma unroll
        for (int p = 0; p < 4; p++) {
            long e = e0 + p * 4 + g;
            long ec = (e < E) ? e : E - 1;
            int s = is64 ? (int)__ldg((const long long*)srcraw + ec)
                         : __ldg((const int*)srcraw + ec);
            int d = is64 ? (int)__ldg((const long long*)dstraw + ec)
                         : __ldg((const int*)dstraw + ec);
            const uint4* Up = (const uint4*)g_Uh + (size_t)s * 16;
            const uint4* Ip = (const uint4*)g_Ih + (size_t)d * 16;
            uint4 u0 = Up[hl], u1 = Up[hl + 8];     // line 0 / line 1
            uint4 v0 = Ip[hl], v1 = Ip[hl + 8];

            uint4 ra, rb;
            {
                const __half2* ua = (const __half2*)&u0;
                const __half2* va = (const __half2*)&v0;
                __half2 h0 = __hmax2(__hadd2(ua[0], va[0]), z2);
                __half2 h1 = __hmax2(__hadd2(ua[1], va[1]), z2);
                __half2 h2 = __hmax2(__hadd2(ua[2], va[2]), z2);
                __half2 h3 = __hmax2(__hadd2(ua[3], va[3]), z2);
                ra = make_uint4(*(unsigned*)&h0, *(unsigned*)&h1,
                                *(unsigned*)&h2, *(unsigned*)&h3);
                const __half2* ub = (const __half2*)&u1;
                const __half2* vb = (const __half2*)&v1;
                __half2 h4 = __hmax2(__hadd2(ub[0], vb[0]), z2);
                __half2 h5 = __hmax2(__hadd2(ub[1], vb[1]), z2);
                __half2 h6 = __hmax2(__hadd2(ub[2], vb[2]), z2);
                __half2 h7 = __hmax2(__hadd2(ub[3], vb[3]), z2);
                rb = make_uint4(*(unsigned*)&h4, *(unsigned*)&h5,
                                *(unsigned*)&h6, *(unsigned*)&h7);
            }
            int r = p * 4 + g;                 // row in tile 0..15
            unsigned sw = (unsigned)((r & 7) << 4);
            unsigned off0 = r * 256 + ((hl * 16) ^ sw);          // k 0..63
            unsigned off1 = r * 256 + ((128 + hl * 16) ^ sw);    // k 64..127
            *(uint4*)(hp + off0) = ra;
            *(uint4*)(hp + off1) = rb;
        }
        __syncwarp();

        // ---- mma over k=128 ----
        float acc0 = 0.f, acc1 = 0.f, acc2 = 0.f, acc3 = 0.f;
        int rr = (lane & 7) + ((lane >> 3) & 1) * 8;   // ldmatrix row
        int khalf = (lane >> 4) * 16;                  // 0 or 16 bytes
        unsigned rowsw = (unsigned)((rr & 7) << 4);
        unsigned abase = su32(hp) + rr * 256;
#pragma unroll
        for (int kt = 0; kt < 8; kt++) {
            unsigned addr = abase + (((unsigned)(kt * 32 + khalf)) ^ rowsw);
            unsigned a0, a1, a2, a3;
            asm volatile("ldmatrix.sync.aligned.m8n8.x4.shared.b16 "
                         "{%0,%1,%2,%3}, [%4];"
                         : "=r"(a0), "=r"(a1), "=r"(a2), "=r"(a3)
                         : "r"(addr));
            asm volatile("mma.sync.aligned.m16n8k16.row.col.f32.f16.f16.f32 "
                         "{%0,%1,%2,%3}, {%4,%5,%6,%7}, {%8,%9}, {%0,%1,%2,%3};"
                         : "+f"(acc0), "+f"(acc1), "+f"(acc2), "+f"(acc3)
                         : "r"(a0), "r"(a1), "r"(a2), "r"(a3),
                           "r"(bfrag[kt][0]), "r"(bfrag[kt][1]));
        }
        __syncwarp();   // protect smem WAR vs next chunk's gather

        // ---- store: c0/c1 -> row lane>>2, cols cA/cB; c2/c3 -> row+8 ----
        long eA = e0 + (lane >> 2);
        long eBr = eA + 8;
        if (cA < NCLS) {
            if (eA < E)  out[eA * NCLS + cA] = acc0 + bA;
            if (eBr < E) out[eBr * NCLS + cA] = acc2 + bA;
        }
        if (cB < NCLS) {
            if (eA < E)  out[eA * NCLS + cB] = acc1 + bB;
            if (eBr < E) out[eBr * NCLS + cB] = acc3 + bB;
        }
    }
}

// ---------------------------------------------------------------------------
// Inputs (metadata order): ufeat, ifeat, W1, b1, W2, b2, src_idx, dst_idx
// ---------------------------------------------------------------------------
extern "C" void kernel_launch(void* const* d_in, const int* in_sizes, int n_in,
                              void* d_out, int out_size) {
    const float* ufeat = (const float*)d_in[0];
    const float* ifeat = (const float*)d_in[1];
    const float* W1    = (const float*)d_in[2];
    const float* b1    = (const float*)d_in[3];
    const float* W2    = (const float*)d_in[4];
    const float* b2    = (const float*)d_in[5];
    const void*  src   = d_in[6];
    const void*  dst   = d_in[7];

    int nu = in_sizes[0] / DD;
    int nm = in_sizes[1] / DD;
    int E  = in_sizes[6];

    int blocksU = (nu + 127) / 128;
    int blocksI = (nm + 127) / 128;
    pre_mma_kernel<<<blocksU + blocksI, 256>>>(ufeat, ifeat, W1, b1, nu, nm, blocksU);

    edge_mma_kernel<<<444, 256>>>(W2, b2, src, dst, (float*)d_out, (long)E);
}